// round 7
// baseline (speedup 1.0000x reference)
#include <cuda_runtime.h>
#include <cstdint>

// Problem constants (from reference setup_inputs)
constexpr int F    = 128;    // n_latent = n_dim
constexpr int HID  = 256;    // hidden
constexpr int NMAX = 50000;
constexpr int EMAX = 800000;

// ---------------------------------------------------------------------------
// Consolidated scratch (two __device__ symbols, manual offsets)
// ---------------------------------------------------------------------------
constexpr size_t OFF_CNT = 0;                    // [NMAX]    in-degree (no self-loop)
constexpr size_t OFF_CUR = NMAX;                 // [NMAX]    fill cursors
constexpr size_t OFF_ROW = 2 * (size_t)NMAX;     // [NMAX+1]  CSR row offsets (by dst)
constexpr size_t OFF_SRC = 3 * (size_t)NMAX + 1; // [EMAX]    CSR src ids
constexpr size_t INT_TOTAL = OFF_SRC + EMAX;

constexpr size_t OFF_ENORM = 0;                              // [EMAX] edge norms
constexpr size_t OFF_DINV  = EMAX;                           // [NMAX]
constexpr size_t OFF_AX    = OFF_DINV + NMAX;                // [NMAX*F]
constexpr size_t OFF_Z1    = OFF_AX + (size_t)NMAX * F;      // [NMAX*HID]
constexpr size_t OFF_H2    = OFF_Z1 + (size_t)NMAX * HID;    // [NMAX*F]
constexpr size_t FLT_TOTAL = OFF_H2 + (size_t)NMAX * F;

__device__ int   g_int[INT_TOTAL];
__device__ float g_flt[FLT_TOTAL];

static inline int cdiv(int a, int b) { return (a + b - 1) / b; }

// ---------------------------------------------------------------------------
// CSR build  (edge_index delivered as int32: ei[0..E) = src, ei[E..2E) = dst)
// ---------------------------------------------------------------------------
__global__ void cnt_zero_kernel(int n) {
    int i = blockIdx.x * blockDim.x + threadIdx.x;
    if (i < n) g_int[OFF_CNT + i] = 0;
}

__global__ void cnt_count_kernel(const int* __restrict__ ei, int E, int N) {
    int e = blockIdx.x * blockDim.x + threadIdx.x;
    if (e < E) {
        int d = ei[(size_t)E + e];
        if (d >= 0 && d < N) atomicAdd(&g_int[OFF_CNT + d], 1);
    }
}

__global__ void dinv_kernel(int n) {
    int i = blockIdx.x * blockDim.x + threadIdx.x;
    if (i < n) g_flt[OFF_DINV + i] = rsqrtf((float)(g_int[OFF_CNT + i] + 1));
}

// Parallel single-block scan: per-thread chunk sums -> warp shfl scans ->
// warp-sum scan -> per-thread rowptr fill. Also zeroes cursors.
__global__ void __launch_bounds__(1024) scan_kernel(int n) {
    __shared__ int wsum[32];
    int t    = threadIdx.x;
    int lane = t & 31;
    int wid  = t >> 5;

    int chunk = (n + 1023) >> 10;
    int start = min(t * chunk, n);
    int end   = min(start + chunk, n);

    int s = 0;
    for (int i = start; i < end; i++) s += g_int[OFF_CNT + i];

    // warp inclusive scan
    int v = s;
#pragma unroll
    for (int off = 1; off < 32; off <<= 1) {
        int u = __shfl_up_sync(0xffffffffu, v, off);
        if (lane >= off) v += u;
    }
    if (lane == 31) wsum[wid] = v;
    __syncthreads();
    if (wid == 0) {
        int w = wsum[lane];
#pragma unroll
        for (int off = 1; off < 32; off <<= 1) {
            int u = __shfl_up_sync(0xffffffffu, w, off);
            if (lane >= off) w += u;
        }
        wsum[lane] = w;
    }
    __syncthreads();

    int warpbase = (wid == 0) ? 0 : wsum[wid - 1];
    int prefix = warpbase + v - s;   // exclusive prefix for this thread's chunk

    for (int i = start; i < end; i++) {
        g_int[OFF_ROW + i] = prefix;
        g_int[OFF_CUR + i] = 0;
        prefix += g_int[OFF_CNT + i];
    }
    if (t == 1023) g_int[OFF_ROW + n] = prefix;  // total E
}

__global__ void fill_kernel(const int* __restrict__ ei, int E, int N) {
    int e = blockIdx.x * blockDim.x + threadIdx.x;
    if (e >= E) return;
    int s = ei[e];
    int d = ei[(size_t)E + e];
    if (s < 0 || s >= N || d < 0 || d >= N) return;
    int pos = g_int[OFF_ROW + d] + atomicAdd(&g_int[OFF_CUR + d], 1);
    g_int[OFF_SRC + pos] = s;
    g_flt[OFF_ENORM + pos] = g_flt[OFF_DINV + s] * g_flt[OFF_DINV + d];
}

// ---------------------------------------------------------------------------
// Pull-mode aggregation: one warp per node, float4 lanes over F=128.
// ---------------------------------------------------------------------------
template <bool BIAS>
__device__ __forceinline__ void gather_body(const float* __restrict__ src_feat,
                                            float* __restrict__ dst_feat,
                                            const float* __restrict__ bias,
                                            int N) {
    int gid  = blockIdx.x * blockDim.x + threadIdx.x;
    int node = gid >> 5;
    int lane = gid & 31;
    if (node >= N) return;

    float dv = g_flt[OFF_DINV + node];
    float selfs = dv * dv;

    float4 v = ((const float4*)(src_feat + (size_t)node * F))[lane];
    float4 acc;
    acc.x = v.x * selfs;
    acc.y = v.y * selfs;
    acc.z = v.z * selfs;
    acc.w = v.w * selfs;
    if (BIAS) {
        float4 b = ((const float4*)bias)[lane];
        acc.x += b.x; acc.y += b.y; acc.z += b.z; acc.w += b.w;
    }

    int beg = g_int[OFF_ROW + node];
    int end = g_int[OFF_ROW + node + 1];
    for (int e = beg; e < end; e++) {
        int   s = g_int[OFF_SRC + e];
        float w = g_flt[OFF_ENORM + e];
        float4 u = ((const float4*)(src_feat + (size_t)s * F))[lane];
        acc.x = fmaf(u.x, w, acc.x);
        acc.y = fmaf(u.y, w, acc.y);
        acc.z = fmaf(u.z, w, acc.z);
        acc.w = fmaf(u.w, w, acc.w);
    }
    ((float4*)(dst_feat + (size_t)node * F))[lane] = acc;
}

__global__ void __launch_bounds__(256)
gather1_kernel(const float* __restrict__ x, int N) {
    gather_body<false>(x, &g_flt[OFF_AX], nullptr, N);
}

__global__ void __launch_bounds__(256)
gather2_kernel(float* __restrict__ out, const float* __restrict__ b2, int N) {
    gather_body<true>(&g_flt[OFF_H2], out, b2, N);
}

// ---------------------------------------------------------------------------
// Tiled fp32 SGEMM: C[M,NO] = A[M,K] @ W[K,NO] (+bias) (relu)
// 128x128 output tile, 256 threads, 8x8 microtile, BK=8
// ---------------------------------------------------------------------------
template <int K, int NO, bool RELU, bool BIAS>
__device__ __forceinline__ void gemm_body(const float* __restrict__ A,
                                          const float* __restrict__ W,
                                          const float* __restrict__ bias,
                                          float* __restrict__ C, int M) {
    constexpr int BM = 128, BN = 128, BK = 8;
    __shared__ float As[BK][BM + 4];   // transposed: As[k][row]
    __shared__ float Ws[BK][BN + 4];   // Ws[k][col]

    int r0 = blockIdx.x * BM;
    int c0 = blockIdx.y * BN;
    int t  = threadIdx.x;
    int tx = t & 15;           // 0..15, col group (8 cols each)
    int ty = t >> 4;           // 0..15, row group (8 rows each)

    // A-load mapping: row = t>>1 (0..127), q = t&1 (which half of the 8 k's)
    int arow = t >> 1;
    int aq   = t & 1;
    // W-load mapping: wr = t>>5 (0..7), wc = t&31 (0..31)
    int wr = t >> 5;
    int wc = t & 31;

    float acc[8][8];
#pragma unroll
    for (int i = 0; i < 8; i++)
#pragma unroll
        for (int j = 0; j < 8; j++) acc[i][j] = 0.f;

    for (int kk = 0; kk < K; kk += BK) {
        {
            float4 v = make_float4(0.f, 0.f, 0.f, 0.f);
            int gr = r0 + arow;
            if (gr < M) v = *(const float4*)(A + (size_t)gr * K + kk + aq * 4);
            As[aq * 4 + 0][arow] = v.x;
            As[aq * 4 + 1][arow] = v.y;
            As[aq * 4 + 2][arow] = v.z;
            As[aq * 4 + 3][arow] = v.w;
        }
        {
            float4 v = *(const float4*)(W + (size_t)(kk + wr) * NO + c0 + wc * 4);
            *(float4*)&Ws[wr][wc * 4] = v;
        }
        __syncthreads();

#pragma unroll
        for (int k = 0; k < BK; k++) {
            float4 a0 = *(const float4*)&As[k][ty * 8];
            float4 a1 = *(const float4*)&As[k][ty * 8 + 4];
            float4 b0 = *(const float4*)&Ws[k][tx * 8];
            float4 b1 = *(const float4*)&Ws[k][tx * 8 + 4];
            float av[8] = {a0.x, a0.y, a0.z, a0.w, a1.x, a1.y, a1.z, a1.w};
            float bv[8] = {b0.x, b0.y, b0.z, b0.w, b1.x, b1.y, b1.z, b1.w};
#pragma unroll
            for (int i = 0; i < 8; i++)
#pragma unroll
                for (int j = 0; j < 8; j++)
                    acc[i][j] = fmaf(av[i], bv[j], acc[i][j]);
        }
        __syncthreads();
    }

    float bb[8] = {0.f, 0.f, 0.f, 0.f, 0.f, 0.f, 0.f, 0.f};
    if (BIAS) {
#pragma unroll
        for (int j = 0; j < 8; j++) bb[j] = bias[c0 + tx * 8 + j];
    }

#pragma unroll
    for (int i = 0; i < 8; i++) {
        int gr = r0 + ty * 8 + i;
        if (gr < M) {
            float o[8];
#pragma unroll
            for (int j = 0; j < 8; j++) {
                o[j] = acc[i][j] + bb[j];
                if (RELU) o[j] = fmaxf(o[j], 0.f);
            }
            float* cp = C + (size_t)gr * NO + c0 + tx * 8;
            *(float4*)(cp)     = make_float4(o[0], o[1], o[2], o[3]);
            *(float4*)(cp + 4) = make_float4(o[4], o[5], o[6], o[7]);
        }
    }
}

// z1 = relu(ax @ W1 + b1)
__global__ void __launch_bounds__(256)
gemm1_kernel(const float* __restrict__ W1, const float* __restrict__ b1, int M) {
    gemm_body<F, HID, true, true>(&g_flt[OFF_AX], W1, b1, &g_flt[OFF_Z1], M);
}

// h2 = z1 @ W2  (bias b2 folded into gather2)
__global__ void __launch_bounds__(256)
gemm2_kernel(const float* __restrict__ W2, int M) {
    gemm_body<HID, F, false, false>(&g_flt[OFF_Z1], W2, nullptr, &g_flt[OFF_H2], M);
}

// ---------------------------------------------------------------------------
// Launch — kernel launches ONLY (graph-capturable)
// ---------------------------------------------------------------------------
extern "C" void kernel_launch(void* const* d_in, const int* in_sizes, int n_in,
                              void* d_out, int out_size) {
    const float* x  = (const float*)d_in[0];
    const int*   ei = (const int*)d_in[1];     // int32 (harness converts int64)
    const float* W1 = (const float*)d_in[2];
    const float* b1 = (const float*)d_in[3];
    const float* W2 = (const float*)d_in[4];
    const float* b2 = (const float*)d_in[5];
    float*       out = (float*)d_out;

    int N = in_sizes[0] / F;
    int E = in_sizes[1] / 2;

    // 1) CSR build + normalization
    cnt_zero_kernel<<<cdiv(N, 256), 256>>>(N);
    cnt_count_kernel<<<cdiv(E, 256), 256>>>(ei, E, N);
    dinv_kernel<<<cdiv(N, 256), 256>>>(N);
    scan_kernel<<<1, 1024>>>(N);
    fill_kernel<<<cdiv(E, 256), 256>>>(ei, E, N);

    // 2) ax = agg(x)  (pull-mode gather, F=128)
    gather1_kernel<<<cdiv(N * 32, 256), 256>>>(x, N);

    // 3) z1 = relu(ax @ W1 + b1)    [N,128]@[128,256]
    {
        dim3 grid(cdiv(N, 128), HID / 128);
        gemm1_kernel<<<grid, 256>>>(W1, b1, N);
    }

    // 4) h2 = z1 @ W2               [N,256]@[256,128]
    {
        dim3 grid(cdiv(N, 128), F / 128);
        gemm2_kernel<<<grid, 256>>>(W2, N);
    }

    // 5) out = b2 + agg(h2)  (pull-mode gather, F=128)
    gather2_kernel<<<cdiv(N * 32, 256), 256>>>(out, b2, N);
}

// round 8
// speedup vs baseline: 1.3276x; 1.3276x over previous
#include <cuda_runtime.h>
#include <cstdint>

// Problem constants (from reference setup_inputs)
constexpr int F    = 128;    // n_latent = n_dim
constexpr int HID  = 256;    // hidden
constexpr int NMAX = 50000;
constexpr int EMAX = 800000;
constexpr int NBMAX = 64;    // max scan blocks (cdiv(50000,1024)=49)

// ---------------------------------------------------------------------------
// Consolidated scratch
// ---------------------------------------------------------------------------
constexpr size_t OFF_CNT  = 0;                      // [NMAX]
constexpr size_t OFF_CUR  = NMAX;                   // [NMAX]
constexpr size_t OFF_ROW  = 2 * (size_t)NMAX;       // [NMAX+1]
constexpr size_t OFF_BSUM = 3 * (size_t)NMAX + 1;   // [NBMAX]
constexpr size_t OFF_SRC  = OFF_BSUM + NBMAX;       // [EMAX]
constexpr size_t INT_TOTAL = OFF_SRC + EMAX;

constexpr size_t OFF_ENORM = 0;                              // [EMAX]
constexpr size_t OFF_DINV  = EMAX;                           // [NMAX]
constexpr size_t OFF_AX    = OFF_DINV + NMAX;                // [NMAX*F]
constexpr size_t OFF_Z1    = OFF_AX + (size_t)NMAX * F;      // [NMAX*HID]
constexpr size_t OFF_H2    = OFF_Z1 + (size_t)NMAX * HID;    // [NMAX*F]
constexpr size_t FLT_TOTAL = OFF_H2 + (size_t)NMAX * F;

__device__ int   g_int[INT_TOTAL];
__device__ float g_flt[FLT_TOTAL];

static inline int cdiv(int a, int b) { return (a + b - 1) / b; }

// ---------------------------------------------------------------------------
// CSR build  (edge_index int32: ei[0..E)=src, ei[E..2E)=dst)
// ---------------------------------------------------------------------------
__global__ void cnt_zero_kernel(int n) {
    int i = blockIdx.x * blockDim.x + threadIdx.x;
    if (i < n) g_int[OFF_CNT + i] = 0;
}

__global__ void cnt_count_kernel(const int* __restrict__ ei, int E, int N) {
    int e = blockIdx.x * blockDim.x + threadIdx.x;
    if (e < E) {
        int d = ei[(size_t)E + e];
        if (d >= 0 && d < N) atomicAdd(&g_int[OFF_CNT + d], 1);
    }
}

__global__ void dinv_kernel(int n) {
    int i = blockIdx.x * blockDim.x + threadIdx.x;
    if (i < n) g_flt[OFF_DINV + i] = rsqrtf((float)(g_int[OFF_CNT + i] + 1));
}

// Scan stage A: per-1024-block sums of g_cnt (coalesced, one elem/thread)
__global__ void __launch_bounds__(1024) blocksum_kernel(int n) {
    int t    = threadIdx.x;
    int lane = t & 31;
    int wid  = t >> 5;
    int i    = blockIdx.x * 1024 + t;
    int v    = (i < n) ? g_int[OFF_CNT + i] : 0;
#pragma unroll
    for (int off = 16; off > 0; off >>= 1)
        v += __shfl_down_sync(0xffffffffu, v, off);
    __shared__ int ws[32];
    if (lane == 0) ws[wid] = v;
    __syncthreads();
    if (wid == 0) {
        int u = ws[lane];
#pragma unroll
        for (int off = 16; off > 0; off >>= 1)
            u += __shfl_down_sync(0xffffffffu, u, off);
        if (lane == 0) g_int[OFF_BSUM + blockIdx.x] = u;
    }
}

// Scan stage B: exclusive-scan the <=NBMAX block sums (tiny, smem-resident)
__global__ void __launch_bounds__(64) bbase_kernel(int nb, int n) {
    __shared__ int sm[NBMAX];
    int t = threadIdx.x;
    if (t < nb) sm[t] = g_int[OFF_BSUM + t];
    __syncthreads();
    if (t == 0) {
        int run = 0;
        for (int i = 0; i < nb; i++) { int c = sm[i]; sm[i] = run; run += c; }
        g_int[OFF_ROW + n] = run;   // total E
    }
    __syncthreads();
    if (t < nb) g_int[OFF_BSUM + t] = sm[t];
}

// Scan stage C: in-block exclusive scan + block base -> rowptr; zero cursors.
__global__ void __launch_bounds__(1024) rowfill_kernel(int n) {
    int t    = threadIdx.x;
    int lane = t & 31;
    int wid  = t >> 5;
    int i    = blockIdx.x * 1024 + t;
    int v    = (i < n) ? g_int[OFF_CNT + i] : 0;

    int incl = v;
#pragma unroll
    for (int off = 1; off < 32; off <<= 1) {
        int u = __shfl_up_sync(0xffffffffu, incl, off);
        if (lane >= off) incl += u;
    }
    __shared__ int ws[32];
    if (lane == 31) ws[wid] = incl;
    __syncthreads();
    if (wid == 0) {
        int w = ws[lane];
#pragma unroll
        for (int off = 1; off < 32; off <<= 1) {
            int u = __shfl_up_sync(0xffffffffu, w, off);
            if (lane >= off) w += u;
        }
        ws[lane] = w;
    }
    __syncthreads();
    int warpbase = (wid == 0) ? 0 : ws[wid - 1];
    int excl = warpbase + incl - v;

    if (i < n) {
        g_int[OFF_ROW + i] = g_int[OFF_BSUM + blockIdx.x] + excl;
        g_int[OFF_CUR + i] = 0;
    }
}

__global__ void fill_kernel(const int* __restrict__ ei, int E, int N) {
    int e = blockIdx.x * blockDim.x + threadIdx.x;
    if (e >= E) return;
    int s = ei[e];
    int d = ei[(size_t)E + e];
    if (s < 0 || s >= N || d < 0 || d >= N) return;
    int pos = g_int[OFF_ROW + d] + atomicAdd(&g_int[OFF_CUR + d], 1);
    g_int[OFF_SRC + pos] = s;
    g_flt[OFF_ENORM + pos] = g_flt[OFF_DINV + s] * g_flt[OFF_DINV + d];
}

// ---------------------------------------------------------------------------
// Pull-mode aggregation: one warp per node, float4 lanes over F=128.
// ---------------------------------------------------------------------------
template <bool BIAS>
__device__ __forceinline__ void gather_body(const float* __restrict__ src_feat,
                                            float* __restrict__ dst_feat,
                                            const float* __restrict__ bias,
                                            int N) {
    int gid  = blockIdx.x * blockDim.x + threadIdx.x;
    int node = gid >> 5;
    int lane = gid & 31;
    if (node >= N) return;

    float dv = g_flt[OFF_DINV + node];
    float selfs = dv * dv;

    float4 v = ((const float4*)(src_feat + (size_t)node * F))[lane];
    float4 acc;
    acc.x = v.x * selfs;
    acc.y = v.y * selfs;
    acc.z = v.z * selfs;
    acc.w = v.w * selfs;
    if (BIAS) {
        float4 b = ((const float4*)bias)[lane];
        acc.x += b.x; acc.y += b.y; acc.z += b.z; acc.w += b.w;
    }

    int beg = g_int[OFF_ROW + node];
    int end = g_int[OFF_ROW + node + 1];
    for (int e = beg; e < end; e++) {
        int   s = g_int[OFF_SRC + e];
        float w = g_flt[OFF_ENORM + e];
        float4 u = ((const float4*)(src_feat + (size_t)s * F))[lane];
        acc.x = fmaf(u.x, w, acc.x);
        acc.y = fmaf(u.y, w, acc.y);
        acc.z = fmaf(u.z, w, acc.z);
        acc.w = fmaf(u.w, w, acc.w);
    }
    ((float4*)(dst_feat + (size_t)node * F))[lane] = acc;
}

__global__ void __launch_bounds__(256)
gather1_kernel(const float* __restrict__ x, int N) {
    gather_body<false>(x, &g_flt[OFF_AX], nullptr, N);
}

__global__ void __launch_bounds__(256)
gather2_kernel(float* __restrict__ out, const float* __restrict__ b2, int N) {
    gather_body<true>(&g_flt[OFF_H2], out, b2, N);
}

// ---------------------------------------------------------------------------
// Tiled fp32 SGEMM (R6-measured-best): 64x64 tile, 256 threads, 4x4 micro, BK=16
// ---------------------------------------------------------------------------
template <int K, int NO, bool RELU, bool BIAS>
__device__ __forceinline__ void gemm_body(const float* __restrict__ A,
                                          const float* __restrict__ W,
                                          const float* __restrict__ bias,
                                          float* __restrict__ C, int M) {
    constexpr int BM = 64, BN = 64, BK = 16;
    __shared__ float As[BK][BM + 4];   // transposed: As[k][row]
    __shared__ float Ws[BK][BN + 4];   // Ws[k][col]

    int r0 = blockIdx.x * BM;
    int c0 = blockIdx.y * BN;
    int t  = threadIdx.x;
    int tx = t & 15;
    int ty = t >> 4;

    float acc[4][4];
    for (int i = 0; i < 4; i++)
        for (int j = 0; j < 4; j++) acc[i][j] = 0.f;

    for (int kk = 0; kk < K; kk += BK) {
        {
            int row = t >> 2;
            int q   = t & 3;
            float4 v = make_float4(0.f, 0.f, 0.f, 0.f);
            int gr = r0 + row;
            if (gr < M) v = *(const float4*)(A + (size_t)gr * K + kk + q * 4);
            As[q * 4 + 0][row] = v.x;
            As[q * 4 + 1][row] = v.y;
            As[q * 4 + 2][row] = v.z;
            As[q * 4 + 3][row] = v.w;
        }
        {
            int r  = t >> 4;
            int c4 = t & 15;
            float4 v = *(const float4*)(W + (size_t)(kk + r) * NO + c0 + c4 * 4);
            Ws[r][c4 * 4 + 0] = v.x;
            Ws[r][c4 * 4 + 1] = v.y;
            Ws[r][c4 * 4 + 2] = v.z;
            Ws[r][c4 * 4 + 3] = v.w;
        }
        __syncthreads();

#pragma unroll
        for (int k = 0; k < BK; k++) {
            float av[4], bv[4];
            for (int i = 0; i < 4; i++) av[i] = As[k][ty * 4 + i];
            for (int j = 0; j < 4; j++) bv[j] = Ws[k][tx * 4 + j];
            for (int i = 0; i < 4; i++)
                for (int j = 0; j < 4; j++)
                    acc[i][j] = fmaf(av[i], bv[j], acc[i][j]);
        }
        __syncthreads();
    }

    float bb[4] = {0.f, 0.f, 0.f, 0.f};
    if (BIAS)
        for (int j = 0; j < 4; j++) bb[j] = bias[c0 + tx * 4 + j];

    for (int i = 0; i < 4; i++) {
        int gr = r0 + ty * 4 + i;
        if (gr < M) {
            float4 o;
            o.x = acc[i][0] + bb[0];
            o.y = acc[i][1] + bb[1];
            o.z = acc[i][2] + bb[2];
            o.w = acc[i][3] + bb[3];
            if (RELU) {
                o.x = fmaxf(o.x, 0.f);
                o.y = fmaxf(o.y, 0.f);
                o.z = fmaxf(o.z, 0.f);
                o.w = fmaxf(o.w, 0.f);
            }
            *(float4*)(C + (size_t)gr * NO + c0 + tx * 4) = o;
        }
    }
}

__global__ void __launch_bounds__(256)
gemm1_kernel(const float* __restrict__ W1, const float* __restrict__ b1, int M) {
    gemm_body<F, HID, true, true>(&g_flt[OFF_AX], W1, b1, &g_flt[OFF_Z1], M);
}

__global__ void __launch_bounds__(256)
gemm2_kernel(const float* __restrict__ W2, int M) {
    gemm_body<HID, F, false, false>(&g_flt[OFF_Z1], W2, nullptr, &g_flt[OFF_H2], M);
}

// ---------------------------------------------------------------------------
// Launch — kernel launches ONLY (graph-capturable)
// ---------------------------------------------------------------------------
extern "C" void kernel_launch(void* const* d_in, const int* in_sizes, int n_in,
                              void* d_out, int out_size) {
    const float* x  = (const float*)d_in[0];
    const int*   ei = (const int*)d_in[1];     // int32 (harness converts int64)
    const float* W1 = (const float*)d_in[2];
    const float* b1 = (const float*)d_in[3];
    const float* W2 = (const float*)d_in[4];
    const float* b2 = (const float*)d_in[5];
    float*       out = (float*)d_out;

    int N = in_sizes[0] / F;
    int E = in_sizes[1] / 2;
    int NB = cdiv(N, 1024);

    // 1) CSR build + normalization (parallel 3-stage scan)
    cnt_zero_kernel<<<cdiv(N, 256), 256>>>(N);
    cnt_count_kernel<<<cdiv(E, 256), 256>>>(ei, E, N);
    dinv_kernel<<<cdiv(N, 256), 256>>>(N);
    blocksum_kernel<<<NB, 1024>>>(N);
    bbase_kernel<<<1, 64>>>(NB, N);
    rowfill_kernel<<<NB, 1024>>>(N);
    fill_kernel<<<cdiv(E, 256), 256>>>(ei, E, N);

    // 2) ax = agg(x)  (pull-mode gather, F=128)
    gather1_kernel<<<cdiv(N * 32, 256), 256>>>(x, N);

    // 3) z1 = relu(ax @ W1 + b1)    [N,128]@[128,256]
    {
        dim3 grid(cdiv(N, 64), HID / 64);
        gemm1_kernel<<<grid, 256>>>(W1, b1, N);
    }

    // 4) h2 = z1 @ W2               [N,256]@[256,128]
    {
        dim3 grid(cdiv(N, 64), F / 64);
        gemm2_kernel<<<grid, 256>>>(W2, N);
    }

    // 5) out = b2 + agg(h2)  (pull-mode gather, F=128)
    gather2_kernel<<<cdiv(N * 32, 256), 256>>>(out, b2, N);
}